// round 10
// baseline (speedup 1.0000x reference)
#include <cuda_runtime.h>

// 2-layer GRU (PyTorch semantics) + linear head. T=512, B=4096, I=2, H=64.
// 128 persistent blocks x 512 threads = 2 independent 256-thread groups of 16
// batch rows (best-known R6 structure, 1 group-barrier/step — 256-WIDE, this
// was the R9 deadlock). Wavefront-optimized SMEM layouts: h is stored as
// [i][q][ks][bg] 16B chunks so every h LDS.128's four lane-chunks are 64
// contiguous bytes (1 wavefront); N-gate weights interleave the two ks halves
// into one 128B window.
// Per-thread tile: 1 j x 8 rows, k-split in-warp (lane bit 4), f32x2 packs
// (even-k, odd-k); k-split reduced by shfl.bfly(16); 4 rows finalized.

#define TT   512
#define BB   4096
#define NBLK 128
#define NTHR 512

typedef unsigned long long u64;

// SMEM (floats):
//  w0  @0      16 i x 768:  [ks0 RZ 256][ks1 RZ 256][N interleaved 256]
//      rz(i,ks,j,gate,e) = i*768 + ks*256 + j*4 + gate*2 + e
//      n(i,ks,j,e)       = i*768 + 512 + (j>>3)*32 + ks*16 + (j&7)*2 + e
//  w1A @12288  same format (Wih1),  w1B @24576 (Whh1)
//  h   @36864  per group 4096: hp0 2 bufs x 1024, hp1 2 bufs x 1024
//      h(i,q,ks,bg,rlo,e) = i*64 + q*16 + ks*8 + bg*4 + rlo*2 + e
//      (i = kp&15, ks = kp>>4, row r = bg*8 + 2q + rlo, e = k parity)
#define OFF_W0  0
#define OFF_W1A 12288
#define OFF_W1B 24576
#define OFF_H   36864
#define SMEM_FLOATS (OFF_H + 2*4096)
#define SMEM_BYTES  (SMEM_FLOATS * 4)   // 180224

__device__ __forceinline__ void ffma2(u64& d, u64 a, u64 b) {
    asm("fma.rn.f32x2 %0, %1, %2, %0;" : "+l"(d) : "l"(a), "l"(b));
}
__device__ __forceinline__ void fadd2(u64& d, u64 a) {
    asm("add.rn.f32x2 %0, %0, %1;" : "+l"(d) : "l"(a));
}
__device__ __forceinline__ float fold(u64 v) {
    float lo, hi;
    asm("mov.b64 {%0,%1}, %2;" : "=f"(lo), "=f"(hi) : "l"(v));
    return lo + hi;
}
__device__ __forceinline__ float tanh_(float x) {
    float r; asm("tanh.approx.f32 %0, %1;" : "=f"(r) : "f"(x)); return r;
}
__device__ __forceinline__ float sigm(float x) {
    return fmaf(tanh_(0.5f * x), 0.5f, 0.5f);
}

// groups are 256 threads wide — barrier count MUST be 256
#define GRPBAR256(id) asm volatile("bar.sync %0, 256;" :: "r"(id) : "memory")

// GEMM over 16 i's. wrz/wn already include (ks, j); hb includes (ks, bg).
__device__ __forceinline__ void gemm16(const float* __restrict__ wrz,
                                       const float* __restrict__ wn,
                                       const float* __restrict__ hb,
                                       u64 aR[8], u64 aZ[8], u64 aN[8])
{
    #pragma unroll 4
    for (int i = 0; i < 16; ++i) {
        u64 wR, wZ;
        {
            ulonglong2 wv = *(const ulonglong2*)(wrz + i * 768);
            wR = wv.x; wZ = wv.y;
        }
        u64 wNv = *(const u64*)(wn + i * 768);
        const float* hr = hb + i * 64;
        ulonglong2 h01 = *(const ulonglong2*)(hr);        // rows 0,1 of my 8
        ulonglong2 h23 = *(const ulonglong2*)(hr + 16);   // rows 2,3
        ulonglong2 h45 = *(const ulonglong2*)(hr + 32);   // rows 4,5
        ulonglong2 h67 = *(const ulonglong2*)(hr + 48);   // rows 6,7
        u64 hv[8] = { h01.x, h01.y, h23.x, h23.y, h45.x, h45.y, h67.x, h67.y };
        #pragma unroll
        for (int b = 0; b < 8; ++b) {
            ffma2(aR[b], hv[b], wR);
            ffma2(aZ[b], hv[b], wZ);
            ffma2(aN[b], hv[b], wNv);
        }
    }
}

__device__ __forceinline__ void stage_w(float* dst, const float* __restrict__ W,
                                        int tid)
{
    for (int idx = tid; idx < 12288; idx += NTHR) {
        int i = idx / 768, r = idx % 768;
        float v;
        if (r < 512) {
            int ks2 = r >> 8, rr = r & 255;
            int j = rr >> 2, gate = (rr >> 1) & 1, e = rr & 1;
            int kp = ks2 * 16 + i;
            v = W[(gate * 64 + j) * 64 + 2 * kp + e];
        } else {
            int rr = r - 512;
            int jg = rr >> 5, w = rr & 31;
            int ks2 = w >> 4, ww = w & 15;
            int j = jg * 8 + (ww >> 1), e = ww & 1;
            int kp = ks2 * 16 + i;
            v = W[(128 + j) * 64 + 2 * kp + e];
        }
        dst[idx] = v;
    }
}

extern "C" __global__ void __launch_bounds__(NTHR, 1)
gru2_kernel(const float* __restrict__ gx,
            const float* __restrict__ Wih0, const float* __restrict__ Whh0,
            const float* __restrict__ bih0, const float* __restrict__ bhh0,
            const float* __restrict__ Wih1, const float* __restrict__ Whh1,
            const float* __restrict__ bih1, const float* __restrict__ bhh1,
            const float* __restrict__ Wp,   const float* __restrict__ bp,
            float* __restrict__ out)
{
    extern __shared__ __align__(16) float sm[];
    const int tid = threadIdx.x;

    // ---- one-time weight staging ----
    stage_w(sm + OFF_W0,  Whh0, tid);
    stage_w(sm + OFF_W1A, Wih1, tid);
    stage_w(sm + OFF_W1B, Whh1, tid);
    for (int i = tid; i < 2 * 4096; i += NTHR) sm[OFF_H + i] = 0.0f;

    // ---- per-thread mapping (R6 structure) ----
    const int g      = tid >> 8;            // group 0/1
    const int gtid   = tid & 255;
    const int warp_g = gtid >> 5;           // 0..7
    const int lane   = tid & 31;
    const int ks     = lane >> 4;           // k-split half
    const int jq     = (lane >> 1) & 7;
    const int bg     = lane & 1;            // 8-row region
    const int j      = warp_g * 8 + jq;     // my j column (0..63)
    const int kpj    = j >> 1, ej = j & 1;
    const int blf0   = bg * 8 + ks * 4;     // first finalized local row
    const int bglob  = blockIdx.x * 32 + g * 16 + blf0;
    const int bar_id = g + 1;

    // gate constants
    const float wxr0 = Wih0[j*2],       wxr1 = Wih0[j*2+1];
    const float wxz0 = Wih0[(64+j)*2],  wxz1 = Wih0[(64+j)*2+1];
    const float wxn0 = Wih0[(128+j)*2], wxn1 = Wih0[(128+j)*2+1];
    const float br0 = bih0[j]    + bhh0[j];
    const float bz0 = bih0[64+j] + bhh0[64+j];
    const float bnx0 = bih0[128+j], bnh0 = bhh0[128+j];
    const float br1 = bih1[j]    + bhh1[j];
    const float bz1 = bih1[64+j] + bhh1[64+j];
    const float bnx1 = bih1[128+j], bnh1 = bhh1[128+j];

    // weight pointers (constant over t)
    const float* w0rz  = sm + OFF_W0  + ks * 256 + j * 4;
    const float* w0n   = sm + OFF_W0  + 512 + (j >> 3) * 32 + ks * 16 + jq * 2;
    const float* w1Arz = sm + OFF_W1A + ks * 256 + j * 4;
    const float* w1An  = sm + OFF_W1A + 512 + (j >> 3) * 32 + ks * 16 + jq * 2;
    const float* w1Brz = sm + OFF_W1B + ks * 256 + j * 4;
    const float* w1Bn  = sm + OFF_W1B + 512 + (j >> 3) * 32 + ks * 16 + jq * 2;

    // group h arrays
    float* hp0 = sm + OFF_H + g * 4096;     // 2 bufs x 1024
    float* hp1 = hp0 + 2048;                // 2 bufs x 1024
    const int hoff = ks * 8 + bg * 4;       // read base within buffer

    // store base: value for (kpj, row r) lives at chunk (kpj&15, q, kpj>>4, r>>3)
    const int st_base = (kpj & 15) * 64 + (kpj >> 4) * 8 + bg * 4 + ej;
    // per finalized i: + (ks*2 + (i>>1))*16 + (i&1)*2

    float hprev0[4] = {0.f, 0.f, 0.f, 0.f};
    float hprev1[4] = {0.f, 0.f, 0.f, 0.f};

    __syncthreads();

    for (int t = 0; t < TT; ++t) {
        const int cur = t & 1, nxt = cur ^ 1;
        float* hp0c = hp0 + cur * 1024;
        float* hp0n = hp0 + nxt * 1024;
        float* hp1c = hp1 + cur * 1024;
        float* hp1n = hp1 + nxt * 1024;

        // x(t) for my 4 finalized rows
        const float* xb = gx + ((size_t)t * BB + bglob) * 2;
        float4 xq0 = *(const float4*)(xb);
        float4 xq1 = *(const float4*)(xb + 4);
        float xf[8] = { xq0.x, xq0.y, xq0.z, xq0.w, xq1.x, xq1.y, xq1.z, xq1.w };

        // ======== G0: layer-0 GEMM, my k-half over hp0[cur] ========
        u64 aR[8], aZ[8], aN[8];
        #pragma unroll
        for (int b = 0; b < 8; ++b) { aR[b] = 0; aZ[b] = 0; aN[b] = 0; }
        gemm16(w0rz, w0n, hp0c + hoff, aR, aZ, aN);

        // ======== E0: k-split reduce + gates; write h0(t) -> hp0[nxt] ========
        #pragma unroll
        for (int i = 0; i < 4; ++i) {
            u64 keepR = ks ? aR[4+i] : aR[i], sndR = ks ? aR[i] : aR[4+i];
            u64 keepZ = ks ? aZ[4+i] : aZ[i], sndZ = ks ? aZ[i] : aZ[4+i];
            u64 keepN = ks ? aN[4+i] : aN[i], sndN = ks ? aN[i] : aN[4+i];
            fadd2(keepR, __shfl_xor_sync(0xffffffffu, sndR, 16));
            fadd2(keepZ, __shfl_xor_sync(0xffffffffu, sndZ, 16));
            fadd2(keepN, __shfl_xor_sync(0xffffffffu, sndN, 16));
            float sR = fold(keepR), sZ = fold(keepZ), sN = fold(keepN);
            float x0 = xf[2*i], x1 = xf[2*i+1];
            float r = sigm(sR + x0 * wxr0 + x1 * wxr1 + br0);
            float z = sigm(sZ + x0 * wxz0 + x1 * wxz1 + bz0);
            float n = tanh_(x0 * wxn0 + x1 * wxn1 + bnx0 + r * (sN + bnh0));
            float h = n + z * (hprev0[i] - n);
            hprev0[i] = h;
            hp0n[st_base + (ks * 2 + (i >> 1)) * 16 + (i & 1) * 2] = h;
        }
        GRPBAR256(bar_id);   // h0(t) visible within group (only bar this step)

        // ======== G1B: layer-1 recurrent half over hp1[cur] (h1(t-1)) ========
        u64 cR[8], cZ[8], cN[8];
        #pragma unroll
        for (int b = 0; b < 8; ++b) { cR[b] = 0; cZ[b] = 0; cN[b] = 0; }
        gemm16(w1Brz, w1Bn, hp1c + hoff, cR, cZ, cN);
        float cNhf[8];
        #pragma unroll
        for (int b = 0; b < 8; ++b) cNhf[b] = fold(cN[b]);   // pre-fold recurrent N

        // ======== G1A: layer-1 input half over hp0[nxt] (fresh h0(t)) ========
        #pragma unroll
        for (int b = 0; b < 8; ++b) cN[b] = 0;
        gemm16(w1Arz, w1An, hp0n + hoff, cR, cZ, cN);

        // ======== E1: exchange + gates; write h1(t) -> hp1[nxt] ========
        #pragma unroll
        for (int i = 0; i < 4; ++i) {
            u64 keepR = ks ? cR[4+i] : cR[i], sndR = ks ? cR[i] : cR[4+i];
            u64 keepZ = ks ? cZ[4+i] : cZ[i], sndZ = ks ? cZ[i] : cZ[4+i];
            u64 keepNx = ks ? cN[4+i] : cN[i], sndNx = ks ? cN[i] : cN[4+i];
            float keepNh = ks ? cNhf[4+i] : cNhf[i];
            float sndNh  = ks ? cNhf[i] : cNhf[4+i];
            fadd2(keepR,  __shfl_xor_sync(0xffffffffu, sndR, 16));
            fadd2(keepZ,  __shfl_xor_sync(0xffffffffu, sndZ, 16));
            fadd2(keepNx, __shfl_xor_sync(0xffffffffu, sndNx, 16));
            float nh = keepNh + __shfl_xor_sync(0xffffffffu, sndNh, 16);
            float sR = fold(keepR), sZ = fold(keepZ), nx = fold(keepNx);
            float r = sigm(sR + br1);
            float z = sigm(sZ + bz1);
            float n = tanh_(nx + bnx1 + r * (nh + bnh1));
            float h = n + z * (hprev1[i] - n);
            hprev1[i] = h;
            hp1n[st_base + (ks * 2 + (i >> 1)) * 16 + (i & 1) * 2] = h;
        }
        // no second barrier: next step's bar orders E1 stores before G1B(t+1);
        // no thread can reach E0(t+1) (writes hp0[cur(t)]) before all group
        // threads passed bar(t), i.e. finished G0(t)'s reads of hp0[cur(t)].
    }

    // ---- projection: out[b] = sum_j Wp[j]*h0f[j] + Wp[64+j]*h1f[j] + bp ----
    GRPBAR256(bar_id + 4);   // group done with its h area
    {
        float* scr = hp0;    // group-local scratch [16 b][stride 68]
        const float wp0 = Wp[j], wp1 = Wp[64 + j];
        #pragma unroll
        for (int i = 0; i < 4; ++i)
            scr[(blf0 + i) * 68 + j] = wp0 * hprev0[i] + wp1 * hprev1[i];
        GRPBAR256(bar_id + 4);
        if (gtid < 16) {
            float s = bp[0];
            #pragma unroll 8
            for (int jj = 0; jj < 64; ++jj) s += scr[gtid * 68 + jj];
            out[blockIdx.x * 32 + g * 16 + gtid] = s;
        }
    }
}

extern "C" void kernel_launch(void* const* d_in, const int* in_sizes, int n_in,
                              void* d_out, int out_size)
{
    (void)in_sizes; (void)n_in; (void)out_size;
    const float* x    = (const float*)d_in[0];
    const float* Wih0 = (const float*)d_in[1];
    const float* Whh0 = (const float*)d_in[2];
    const float* bih0 = (const float*)d_in[3];
    const float* bhh0 = (const float*)d_in[4];
    const float* Wih1 = (const float*)d_in[5];
    const float* Whh1 = (const float*)d_in[6];
    const float* bih1 = (const float*)d_in[7];
    const float* bhh1 = (const float*)d_in[8];
    const float* Wp   = (const float*)d_in[9];
    const float* bp   = (const float*)d_in[10];
    float* out = (float*)d_out;

    cudaFuncSetAttribute(gru2_kernel, cudaFuncAttributeMaxDynamicSharedMemorySize, SMEM_BYTES);
    gru2_kernel<<<NBLK, NTHR, SMEM_BYTES>>>(x, Wih0, Whh0, bih0, bhh0,
                                            Wih1, Whh1, bih1, bhh1, Wp, bp, out);
}

// round 11
// speedup vs baseline: 1.1334x; 1.1334x over previous
#include <cuda_runtime.h>

// 2-layer GRU (PyTorch semantics) + linear head. T=512, B=4096, I=2, H=64.
// 148 persistent blocks x 512 threads — uses ALL SMs. Each block owns 28
// batch rows (batch padded to 148*28=4144; x reads clamped, out predicated).
// Block = 2 independent 256-thread groups of 14 rows (R6 structure, 1 group
// barrier/step). Group = 8 warps: warps 0-3 handle an 8-row region (B8 tile,
// identical to the best R6 tile), warps 4-7 a 6-row region (B6 tile) —
// region is warp-level so both paths are warp-uniform.
// Per-thread: 1 j x NB rows GEMM, in-warp k-split (lane bit 4), f32x2 packs
// (even-k, odd-k); k-split reduced by shfl.bfly(16); NB/2 rows finalized.

#define TT   512
#define BB   4096
#define NBLK 148
#define NTHR 512

typedef unsigned long long u64;

// SMEM (floats):
//  w0 [32 kp][384]: per kp: RZ (64 j x {R u64, Z u64}) + N (64 j x u64) @+256
//  w1 [64 kp][384]: kp<32 = Wih1, kp>=32 = Whh1
//  h  @36864, per group 3584: hp0 2 bufs x 896, hp1 2 bufs x 896
//     row layout per kp: 28 floats = [bg0: 8 rows x2][bg1: 6 rows x2]
#define OFF_W0 0
#define OFF_W1 12288
#define OFF_H  36864
#define GRPH   3584
#define SMEM_FLOATS (OFF_H + 2*GRPH)     // 44032
#define SMEM_BYTES  (SMEM_FLOATS * 4)    // 176128

__device__ __forceinline__ void ffma2(u64& d, u64 a, u64 b) {
    asm("fma.rn.f32x2 %0, %1, %2, %0;" : "+l"(d) : "l"(a), "l"(b));
}
__device__ __forceinline__ void fadd2(u64& d, u64 a) {
    asm("add.rn.f32x2 %0, %0, %1;" : "+l"(d) : "l"(a));
}
__device__ __forceinline__ float fold(u64 v) {
    float lo, hi;
    asm("mov.b64 {%0,%1}, %2;" : "=f"(lo), "=f"(hi) : "l"(v));
    return lo + hi;
}
__device__ __forceinline__ float tanh_(float x) {
    float r; asm("tanh.approx.f32 %0, %1;" : "=f"(r) : "f"(x)); return r;
}
__device__ __forceinline__ float sigm(float x) {
    return fmaf(tanh_(0.5f * x), 0.5f, 0.5f);
}

#define GRPBAR256(id) asm volatile("bar.sync %0, 256;" :: "r"(id) : "memory")

// GEMM over NKP k-pairs, NB rows. wrz = base + j*4 (stride 384), wn = +256+j*2.
// hb = h base (stride 28 floats/kp) + region offset.
template<int NKP, int NB>
__device__ __forceinline__ void gemm_rzn(const float* __restrict__ wrz,
                                         const float* __restrict__ wn,
                                         const float* __restrict__ hb,
                                         u64 aR[NB], u64 aZ[NB], u64 aN[NB])
{
    #pragma unroll 4
    for (int kp = 0; kp < NKP; ++kp) {
        ulonglong2 wv = *(const ulonglong2*)(wrz + kp * 384);
        u64 wNv = *(const u64*)(wn + kp * 384);
        const float* hr = hb + kp * 28;
        u64 hv[NB];
        {
            ulonglong2 t0 = *(const ulonglong2*)(hr);
            ulonglong2 t1 = *(const ulonglong2*)(hr + 4);
            hv[0] = t0.x; hv[1] = t0.y; hv[2] = t1.x; hv[3] = t1.y;
            if constexpr (NB == 8) {
                ulonglong2 t2 = *(const ulonglong2*)(hr + 8);
                ulonglong2 t3 = *(const ulonglong2*)(hr + 12);
                hv[4] = t2.x; hv[5] = t2.y; hv[6] = t3.x; hv[7] = t3.y;
            } else {
                ulonglong2 t2 = *(const ulonglong2*)(hr + 8);
                hv[4] = t2.x; hv[5] = t2.y;
            }
        }
        #pragma unroll
        for (int b = 0; b < NB; ++b) {
            ffma2(aR[b], hv[b], wv.x);
            ffma2(aZ[b], hv[b], wv.y);
            ffma2(aN[b], hv[b], wNv);
        }
    }
}

struct Ctx {
    const float* gx;
    float* hp0; float* hp1;
    const float* w0rz; const float* w0n;
    const float* w1rz; const float* w1n;
    int ks, bgf, st0, bglob, bar_id;
    float wxr0, wxr1, wxz0, wxz1, wxn0, wxn1;
    float br0, bz0, bnx0, bnh0, br1, bz1, bnx1, bnh1;
};

template<int NB>
__device__ __forceinline__ void time_loop(const Ctx c, float* hprev0, float* hprev1)
{
    constexpr int F = NB / 2;
    const int ks = c.ks;
    for (int t = 0; t < TT; ++t) {
        const int cur = t & 1, nxt = cur ^ 1;
        float* hp0c = c.hp0 + cur * 896;
        float* hp0n = c.hp0 + nxt * 896;
        float* hp1c = c.hp1 + cur * 896;
        float* hp1n = c.hp1 + nxt * 896;

        // x(t) for my F finalized rows (clamped for the padded tail rows)
        float xf[2 * F];
        #pragma unroll
        for (int i = 0; i < F; ++i) {
            int br = c.bglob + i; if (br > BB - 1) br = BB - 1;
            float2 v = *(const float2*)(c.gx + ((size_t)t * BB + br) * 2);
            xf[2 * i] = v.x; xf[2 * i + 1] = v.y;
        }

        // ======== G0: layer-0 GEMM, my k-half over hp0[cur] ========
        u64 aR[NB], aZ[NB], aN[NB];
        #pragma unroll
        for (int b = 0; b < NB; ++b) { aR[b] = 0; aZ[b] = 0; aN[b] = 0; }
        gemm_rzn<16, NB>(c.w0rz, c.w0n, hp0c + ks * 448 + c.bgf, aR, aZ, aN);

        // ======== E0: k-split reduce + gates; write h0(t) -> hp0[nxt] ========
        #pragma unroll
        for (int i = 0; i < F; ++i) {
            u64 keepR = ks ? aR[F+i] : aR[i], sndR = ks ? aR[i] : aR[F+i];
            u64 keepZ = ks ? aZ[F+i] : aZ[i], sndZ = ks ? aZ[i] : aZ[F+i];
            u64 keepN = ks ? aN[F+i] : aN[i], sndN = ks ? aN[i] : aN[F+i];
            fadd2(keepR, __shfl_xor_sync(0xffffffffu, sndR, 16));
            fadd2(keepZ, __shfl_xor_sync(0xffffffffu, sndZ, 16));
            fadd2(keepN, __shfl_xor_sync(0xffffffffu, sndN, 16));
            float sR = fold(keepR), sZ = fold(keepZ), sN = fold(keepN);
            float x0 = xf[2*i], x1 = xf[2*i+1];
            float r = sigm(sR + x0 * c.wxr0 + x1 * c.wxr1 + c.br0);
            float z = sigm(sZ + x0 * c.wxz0 + x1 * c.wxz1 + c.bz0);
            float n = tanh_(x0 * c.wxn0 + x1 * c.wxn1 + c.bnx0 + r * (sN + c.bnh0));
            float h = n + z * (hprev0[i] - n);
            hprev0[i] = h;
            hp0n[c.st0 + i * 2] = h;
        }
        GRPBAR256(c.bar_id);   // h0(t) visible within group (only bar this step)

        // ==== G1: layer-1 GEMM. ks0: input side (Wih1) over hp0[nxt] (fresh h0);
        //          ks1: recurrent (Whh1) over hp1[cur]. 32 kp each. ====
        u64 cR[NB], cZ[NB], cN[NB];
        #pragma unroll
        for (int b = 0; b < NB; ++b) { cR[b] = 0; cZ[b] = 0; cN[b] = 0; }
        gemm_rzn<32, NB>(c.w1rz, c.w1n, (ks ? hp1c : hp0n) + c.bgf, cR, cZ, cN);

        // ======== E1: exchange + gates; write h1(t) -> hp1[nxt] ========
        #pragma unroll
        for (int i = 0; i < F; ++i) {
            u64 keepR = ks ? cR[F+i] : cR[i], sndR = ks ? cR[i] : cR[F+i];
            u64 keepZ = ks ? cZ[F+i] : cZ[i], sndZ = ks ? cZ[i] : cZ[F+i];
            u64 keepN = ks ? cN[F+i] : cN[i], sndN = ks ? cN[i] : cN[F+i];
            fadd2(keepR, __shfl_xor_sync(0xffffffffu, sndR, 16));
            fadd2(keepZ, __shfl_xor_sync(0xffffffffu, sndZ, 16));
            u64 rcvN = __shfl_xor_sync(0xffffffffu, sndN, 16);
            float sR = fold(keepR), sZ = fold(keepZ);
            float fm = fold(keepN), fr = fold(rcvN);
            float nx = ks ? fr : fm;      // input-side partial came from ks0
            float nh = ks ? fm : fr;      // recurrent partial came from ks1
            float r = sigm(sR + c.br1);
            float z = sigm(sZ + c.bz1);
            float n = tanh_(nx + c.bnx1 + r * (nh + c.bnh1));
            float h = n + z * (hprev1[i] - n);
            hprev1[i] = h;
            hp1n[c.st0 + i * 2] = h;
        }
        // no second barrier: next step's bar (after E0) orders E1 stores before
        // G1(t+1) reads hp1, and hp0[cur]'s reuse in E0(t+1) after G0(t)'s reads.
    }
}

extern "C" __global__ void __launch_bounds__(NTHR, 1)
gru2_kernel(const float* __restrict__ gx,
            const float* __restrict__ Wih0, const float* __restrict__ Whh0,
            const float* __restrict__ bih0, const float* __restrict__ bhh0,
            const float* __restrict__ Wih1, const float* __restrict__ Whh1,
            const float* __restrict__ bih1, const float* __restrict__ bhh1,
            const float* __restrict__ Wp,   const float* __restrict__ bp,
            float* __restrict__ out)
{
    extern __shared__ __align__(16) float sm[];
    const int tid = threadIdx.x;

    // ---- one-time weight staging (R6 layout) ----
    for (int i = tid; i < 12288; i += NTHR) {
        int kp = i / 384, r = i % 384;
        float v;
        if (r < 256) {
            int j = r >> 2, sub = r & 3, gate = sub >> 1, e = sub & 1;
            v = Whh0[(gate * 64 + j) * 64 + 2 * kp + e];
        } else {
            int rr = r - 256, j = rr >> 1, e = rr & 1;
            v = Whh0[(128 + j) * 64 + 2 * kp + e];
        }
        sm[OFF_W0 + i] = v;
    }
    for (int i = tid; i < 24576; i += NTHR) {
        int kp = i / 384, r = i % 384;
        const float* W = (kp < 32) ? Wih1 : Whh1;
        int k0 = 2 * (kp & 31);
        float v;
        if (r < 256) {
            int j = r >> 2, sub = r & 3, gate = sub >> 1, e = sub & 1;
            v = W[(gate * 64 + j) * 64 + k0 + e];
        } else {
            int rr = r - 256, j = rr >> 1, e = rr & 1;
            v = W[(128 + j) * 64 + k0 + e];
        }
        sm[OFF_W1 + i] = v;
    }
    for (int i = tid; i < 2 * GRPH; i += NTHR) sm[OFF_H + i] = 0.0f;

    // ---- per-thread mapping ----
    const int warp   = tid >> 5;
    const int g      = tid >> 8;            // group 0/1 (warps 0-7 | 8-15)
    const int warp_g = warp & 7;
    const int jw     = warp_g & 3;          // 4 j-warps cover 64 j
    const int bg     = warp_g >> 2;         // region: 0 = 8 rows, 1 = 6 rows
    const int lane   = tid & 31;
    const int ks     = lane >> 4;
    const int jq     = lane & 15;
    const int j      = jw * 16 + jq;        // my j column (0..63)
    const int kpj    = j >> 1, ej = j & 1;
    const int F      = bg ? 3 : 4;
    const int lrow0  = bg * 8 + ks * F;     // first finalized local row (of 14)
    const int bglob  = blockIdx.x * 28 + g * 14 + lrow0;
    const int bar_id = g + 1;

    Ctx c;
    c.gx = gx;
    c.ks = ks;
    c.bgf = bg * 16;
    c.st0 = kpj * 28 + lrow0 * 2 + ej;
    c.bglob = bglob;
    c.bar_id = bar_id;

    c.wxr0 = Wih0[j*2];        c.wxr1 = Wih0[j*2+1];
    c.wxz0 = Wih0[(64+j)*2];   c.wxz1 = Wih0[(64+j)*2+1];
    c.wxn0 = Wih0[(128+j)*2];  c.wxn1 = Wih0[(128+j)*2+1];
    c.br0 = bih0[j]    + bhh0[j];
    c.bz0 = bih0[64+j] + bhh0[64+j];
    c.bnx0 = bih0[128+j]; c.bnh0 = bhh0[128+j];
    c.br1 = bih1[j]    + bhh1[j];
    c.bz1 = bih1[64+j] + bhh1[64+j];
    c.bnx1 = bih1[128+j]; c.bnh1 = bhh1[128+j];

    c.w0rz = sm + OFF_W0 + (ks * 16) * 384 + j * 4;
    c.w0n  = sm + OFF_W0 + (ks * 16) * 384 + 256 + j * 2;
    c.w1rz = sm + OFF_W1 + (ks * 32) * 384 + j * 4;   // ks0: Wih1, ks1: Whh1
    c.w1n  = sm + OFF_W1 + (ks * 32) * 384 + 256 + j * 2;

    c.hp0 = sm + OFF_H + g * GRPH;          // 2 bufs x 896
    c.hp1 = c.hp0 + 1792;                   // 2 bufs x 896

    float hprev0[4] = {0.f, 0.f, 0.f, 0.f};
    float hprev1[4] = {0.f, 0.f, 0.f, 0.f};

    __syncthreads();

    if (bg == 0) time_loop<8>(c, hprev0, hprev1);
    else         time_loop<6>(c, hprev0, hprev1);

    // ---- projection: out[b] = sum_j Wp[j]*h0f[j] + Wp[64+j]*h1f[j] + bp ----
    __syncthreads();   // all groups done with h buffers
    {
        float* scr = sm + OFF_H;   // [28 rows][stride 68]
        const float wp0 = Wp[j], wp1 = Wp[64 + j];
        #pragma unroll
        for (int i = 0; i < 4; ++i) {
            if (i < F) {
                int lr = g * 14 + lrow0 + i;
                scr[lr * 68 + j] = wp0 * hprev0[i] + wp1 * hprev1[i];
            }
        }
        __syncthreads();
        if (tid < 28) {
            int rowg = blockIdx.x * 28 + tid;
            if (rowg < BB) {
                float s = bp[0];
                #pragma unroll 8
                for (int jj = 0; jj < 64; ++jj) s += scr[tid * 68 + jj];
                out[rowg] = s;
            }
        }
    }
}

extern "C" void kernel_launch(void* const* d_in, const int* in_sizes, int n_in,
                              void* d_out, int out_size)
{
    (void)in_sizes; (void)n_in; (void)out_size;
    const float* x    = (const float*)d_in[0];
    const float* Wih0 = (const float*)d_in[1];
    const float* Whh0 = (const float*)d_in[2];
    const float* bih0 = (const float*)d_in[3];
    const float* bhh0 = (const float*)d_in[4];
    const float* Wih1 = (const float*)d_in[5];
    const float* Whh1 = (const float*)d_in[6];
    const float* bih1 = (const float*)d_in[7];
    const float* bhh1 = (const float*)d_in[8];
    const float* Wp   = (const float*)d_in[9];
    const float* bp   = (const float*)d_in[10];
    float* out = (float*)d_out;

    cudaFuncSetAttribute(gru2_kernel, cudaFuncAttributeMaxDynamicSharedMemorySize, SMEM_BYTES);
    gru2_kernel<<<NBLK, NTHR, SMEM_BYTES>>>(x, Wih0, Whh0, bih0, bhh0,
                                            Wih1, Whh1, bih1, bhh1, Wp, bp, out);
}